// round 15
// baseline (speedup 1.0000x reference)
#include <cuda_runtime.h>
#include <cuda_fp16.h>
#include <math.h>
#include <cstdint>

// ---------------- problem constants ----------------
constexpr int BATCH = 64;
constexpr int TFULL = 2049;
constexpr int TCTX  = 2048;
constexpr int D     = 512;
constexpr int D2    = 1024;
constexpr int VOCAB = 50257;
constexpr int MTOK  = BATCH * TFULL;   // 131136

// ---------------- scratch (device globals) ----------------
__device__ __half  g_Hx [(size_t)MTOK * D];    // x = h + ff, fp16 (written by GEMM2)
__device__ __half  g_Hh [(size_t)MTOK * D];
__device__ __half  g_A1h[(size_t)MTOK * D2];
__device__ __half  g_W1h[(size_t)D2 * D];      // W1^T fp16  [N=D2, K=D]
__device__ __half  g_W2h[(size_t)D * D2];      // W2^T fp16  [N=D,  K=D2]
__device__ float   g_LNP[(size_t)MTOK * 3];    // per-row partials: Sx, Sxx, SxgW
__device__ float   g_GW [D];                   // gamma*Wg
__device__ float   g_CONST[2];                 // {sum(gamma*Wg), sum(beta*Wg)}
__device__ int     g_IDX [BATCH * 3];
__device__ float   g_CTX [BATCH * D];

// ---------------- PTX helpers (base-target features only) ----------------
__device__ __forceinline__ unsigned smem_u32(const void* p) {
    unsigned a;
    asm("{ .reg .u64 t; cvta.to.shared.u64 t, %1; cvt.u32.u64 %0, t; }" : "=r"(a) : "l"(p));
    return a;
}
__device__ __forceinline__ void cp16(unsigned dst, const void* src, int sz) {
    asm volatile("cp.async.cg.shared.global [%0], [%1], 16, %2;"
                 :: "r"(dst), "l"(src), "r"(sz) : "memory");
}
__device__ __forceinline__ void ldsm4(unsigned& r0, unsigned& r1, unsigned& r2, unsigned& r3,
                                      unsigned addr) {
    asm volatile("ldmatrix.sync.aligned.m8n8.x4.shared.b16 {%0,%1,%2,%3}, [%4];"
                 : "=r"(r0), "=r"(r1), "=r"(r2), "=r"(r3) : "r"(addr));
}
__device__ __forceinline__ void mma_f16(float* c, const unsigned* a, const unsigned* b) {
    asm volatile("mma.sync.aligned.m16n8k16.row.col.f32.f16.f16.f32 "
                 "{%0,%1,%2,%3}, {%4,%5,%6,%7}, {%8,%9}, {%0,%1,%2,%3};"
                 : "+f"(c[0]), "+f"(c[1]), "+f"(c[2]), "+f"(c[3])
                 : "r"(a[0]), "r"(a[1]), "r"(a[2]), "r"(a[3]), "r"(b[0]), "r"(b[1]));
}
__device__ __forceinline__ unsigned pack_half2(float v0, float v1) {
    __half h0 = __float2half_rn(v0);
    __half h1 = __float2half_rn(v1);
    return (unsigned)__half_as_ushort(h0) | ((unsigned)__half_as_ushort(h1) << 16);
}

// ---------------- weight prep: transpose + fp16 round ----------------
__global__ void wprep(const float* __restrict__ W, __half* __restrict__ Bh, int K, int N)
{
    int i = blockIdx.x * 256 + threadIdx.x;
    if (i >= K * N) return;
    int k = i / N, n = i - k * N;
    Bh[(size_t)n * K + k] = __float2half_rn(W[i]);
}

// ---------------- prep: gamma*Wg array + scalar constants ----------------
__global__ void prep_gw(const float* __restrict__ gamma, const float* __restrict__ beta,
                        const float* __restrict__ Wg)
{
    int t = threadIdx.x;                    // 512 threads
    float gw = gamma[t] * Wg[t];
    float bw = beta[t]  * Wg[t];
    g_GW[t] = gw;
    __shared__ float s1[16], s2[16];
    #pragma unroll
    for (int o = 16; o > 0; o >>= 1) {
        gw += __shfl_xor_sync(0xffffffffu, gw, o);
        bw += __shfl_xor_sync(0xffffffffu, bw, o);
    }
    int lane = t & 31, w = t >> 5;
    if (lane == 0) { s1[w] = gw; s2[w] = bw; }
    __syncthreads();
    if (t == 0) {
        float a = 0.f, b = 0.f;
        #pragma unroll
        for (int i = 0; i < 16; i++) { a += s1[i]; b += s2[i]; }
        g_CONST[0] = a; g_CONST[1] = b;
    }
}

// ---------------- gather: warp-per-row embed lookup -> fp16; zero LN partials ----------------
__global__ __launch_bounds__(256) void gather_kernel(const int* __restrict__ seq,
                                                     const float* __restrict__ embed)
{
    int w = threadIdx.x >> 5, lane = threadIdx.x & 31;
    int m = blockIdx.x * 8 + w;             // MTOK divisible by 8
    int tok = seq[m];
    if (lane < 3) g_LNP[(size_t)m * 3 + lane] = 0.f;
    const float4* src = reinterpret_cast<const float4*>(embed + (size_t)tok * D);
    uint2* dstHh = reinterpret_cast<uint2*>(g_Hh + (size_t)m * D);
    #pragma unroll
    for (int i = 0; i < 4; i++) {
        int j = lane + 32 * i;
        float4 v = src[j];
        uint2 p;
        p.x = pack_half2(v.x, v.y);
        p.y = pack_half2(v.z, v.w);
        dstHh[j] = p;
    }
}

// ---------------- mma.sync fp16 GEMM, CTA 128x128, warp 32x64, BK=32, 4-stage ----------------
// Conflict-free smem: 48-byte row stride. Slice (k16) = 128*48 = 6144B.
// Stage = A[2 slices] + B[2 slices] = 24576B. A slice s at s*6144; B at 12288+s*6144.
// 4 stages = 98304B -> 2 CTAs/SM.
// Wait ladder (CORRECT): at iter c, only stages c+1, c+2 may be pending -> wait_group 2.
// MODE 0: relu -> fp16 out.  MODE 1: +bias + embed residual -> fp16 x out + LN partials.
constexpr int SLICE_BYTES = 6144;
constexpr int STAGE_BYTES = 24576;
constexpr int GEMM_SMEM   = 4 * STAGE_BYTES;   // 98304

__device__ __forceinline__ void fill_stage(unsigned sb,
    const __half* __restrict__ Ah, const __half* __restrict__ Bh,
    int K, int m0, int M, int n0, int kc, int tid)
{
    int r = tid >> 1, half = tid & 1;
    int arow = m0 + r;
    int asz  = (arow < M) ? 16 : 0;
    size_t aoff = (size_t)(asz ? arow : 0) * K + kc + half * 8;
    size_t boff = (size_t)(n0 + r) * K + kc + half * 8;
    unsigned dst = sb + r * 48 + half * 16;
    #pragma unroll
    for (int s = 0; s < 2; s++) {
        cp16(dst + s * SLICE_BYTES,         Ah + aoff + s * 16, asz);
        cp16(dst + 12288 + s * SLICE_BYTES, Bh + boff + s * 16, 16);
    }
    asm volatile("cp.async.commit_group;" ::: "memory");
}

template<int MODE>
__global__ __launch_bounds__(256, 2) void ff_gemm(
    const __half* __restrict__ Ah, const __half* __restrict__ Bh,
    const float* __restrict__ bias,
    const int* __restrict__ seq, const float* __restrict__ embed,
    __half* __restrict__ Ch, int M, int N, int K)
{
    extern __shared__ __align__(128) char smem[];
    unsigned sb = smem_u32(smem);
    const int tid = threadIdx.x, lane = tid & 31, wid = tid >> 5;
    const int wm = wid & 3, wn = wid >> 2;
    const int m0 = blockIdx.y * 128, n0 = blockIdx.x * 128;

    // per-lane ldmatrix offsets (within a k16-slice; 48B row stride)
    const unsigned aO = (unsigned)((wm * 32 + (lane & 15)) * 48 + (lane >> 4) * 16);
    const unsigned bO = 12288u +
        (unsigned)((wn * 64 + (lane >> 4) * 8 + (lane & 7)) * 48 + ((lane >> 3) & 1) * 16);

    float acc[2][8][4];
    #pragma unroll
    for (int i = 0; i < 2; i++)
        #pragma unroll
        for (int j = 0; j < 8; j++)
            #pragma unroll
            for (int q = 0; q < 4; q++) acc[i][j][q] = 0.f;

    const int NC = K >> 5;
    fill_stage(sb + 0 * STAGE_BYTES, Ah, Bh, K, m0, M, n0, 0,  tid);
    fill_stage(sb + 1 * STAGE_BYTES, Ah, Bh, K, m0, M, n0, 32, tid);
    fill_stage(sb + 2 * STAGE_BYTES, Ah, Bh, K, m0, M, n0, 64, tid);

    int sidx = 0;
    for (int c = 0; c < NC; c++) {
        int rem = NC - 1 - c;
        // stage c complete; only c+1, c+2 may remain pending
        if (rem >= 2)      asm volatile("cp.async.wait_group 2;" ::: "memory");
        else if (rem == 1) asm volatile("cp.async.wait_group 1;" ::: "memory");
        else               asm volatile("cp.async.wait_group 0;" ::: "memory");
        __syncthreads();

        unsigned st = sb + sidx * STAGE_BYTES;

        // slice 0 loads first (start LDS latency ASAP)
        unsigned ah[2][4], bh[8][2];
        #pragma unroll
        for (int mt = 0; mt < 2; mt++)
            ldsm4(ah[mt][0], ah[mt][1], ah[mt][2], ah[mt][3], st + aO + mt * 768);
        #pragma unroll
        for (int pr = 0; pr < 4; pr++)
            ldsm4(bh[2*pr][0], bh[2*pr][1], bh[2*pr+1][0], bh[2*pr+1][1],
                  st + bO + pr * 768);

        // prefetch next stage while slice-0 fragments are in flight
        int pf = c + 3;
        if (pf < NC) {
            int psidx = sidx + 3; if (psidx >= 4) psidx -= 4;
            fill_stage(sb + psidx * STAGE_BYTES, Ah, Bh, K, m0, M, n0, pf * 32, tid);
        }

        #pragma unroll
        for (int mt = 0; mt < 2; mt++)
            #pragma unroll
            for (int nt = 0; nt < 8; nt++)
                mma_f16(acc[mt][nt], ah[mt], bh[nt]);

        // slice 1
        #pragma unroll
        for (int mt = 0; mt < 2; mt++)
            ldsm4(ah[mt][0], ah[mt][1], ah[mt][2], ah[mt][3],
                  st + SLICE_BYTES + aO + mt * 768);
        #pragma unroll
        for (int pr = 0; pr < 4; pr++)
            ldsm4(bh[2*pr][0], bh[2*pr][1], bh[2*pr+1][0], bh[2*pr+1][1],
                  st + SLICE_BYTES + bO + pr * 768);
        #pragma unroll
        for (int mt = 0; mt < 2; mt++)
            #pragma unroll
            for (int nt = 0; nt < 8; nt++)
                mma_f16(acc[mt][nt], ah[mt], bh[nt]);

        if (++sidx == 4) sidx = 0;
    }

    // ---------------- epilogue ----------------
    const int g = lane >> 2, t4 = lane & 3;
    #pragma unroll
    for (int mt = 0; mt < 2; mt++) {
        int r0 = m0 + wm * 32 + mt * 16 + g;
        bool v0 = (r0 < M), v1 = (r0 + 8 < M);
        if (MODE == 0) {
            #pragma unroll
            for (int nt = 0; nt < 8; nt++) {
                int n = n0 + wn * 64 + nt * 8 + t4 * 2;
                float b0 = bias[n], b1 = bias[n + 1];
                if (v0)
                    *reinterpret_cast<unsigned*>(Ch + (size_t)r0 * N + n) =
                        pack_half2(fmaxf(acc[mt][nt][0] + b0, 0.f),
                                   fmaxf(acc[mt][nt][1] + b1, 0.f));
                if (v1)
                    *reinterpret_cast<unsigned*>(Ch + (size_t)(r0 + 8) * N + n) =
                        pack_half2(fmaxf(acc[mt][nt][2] + b0, 0.f),
                                   fmaxf(acc[mt][nt][3] + b1, 0.f));
            }
        } else {
            int tok0 = v0 ? seq[r0] : 0;
            int tok1 = v1 ? seq[r0 + 8] : 0;
            float sA1 = 0.f, sA2 = 0.f, sA3 = 0.f;
            float sB1 = 0.f, sB2 = 0.f, sB3 = 0.f;
            #pragma unroll
            for (int nt = 0; nt < 8; nt++) {
                int n = n0 + wn * 64 + nt * 8 + t4 * 2;
                float b0 = bias[n], b1 = bias[n + 1];
                float2 gw = *reinterpret_cast<const float2*>(g_GW + n);
                if (v0) {
                    float2 a = *reinterpret_cast<const float2*>(embed + (size_t)tok0 * D + n);
                    float x0 = acc[mt][nt][0] + b0 + a.x;
                    float x1 = acc[mt][nt][1] + b1 + a.y;
                    *reinterpret_cast<unsigned*>(Ch + (size_t)r0 * N + n) = pack_half2(x0, x1);
                    sA1 += x0 + x1; sA2 += x0 * x0 + x1 * x1;
                    sA3 += x0 * gw.x + x1 * gw.y;
                }
                if (v1) {
                    float2 a = *reinterpret_cast<const float2*>(embed + (size_t)tok1 * D + n);
                    float x0 = acc[mt][nt][2] + b0 + a.x;
                    float x1 = acc[mt][nt][3] + b1 + a.y;
                    *reinterpret_cast<unsigned*>(Ch + (size_t)(r0 + 8) * N + n) = pack_half2(x0, x1);
                    sB1 += x0 + x1; sB2 += x0 * x0 + x1 * x1;
                    sB3 += x0 * gw.x + x1 * gw.y;
                }
            }
            #pragma unroll
            for (int o = 1; o < 4; o <<= 1) {
                sA1 += __shfl_down_sync(0xffffffffu, sA1, o);
                sA2 += __shfl_down_sync(0xffffffffu, sA2, o);
                sA3 += __shfl_down_sync(0xffffffffu, sA3, o);
                sB1 += __shfl_down_sync(0xffffffffu, sB1, o);
                sB2 += __shfl_down_sync(0xffffffffu, sB2, o);
                sB3 += __shfl_down_sync(0xffffffffu, sB3, o);
            }
            if (t4 == 0) {
                if (v0) {
                    atomicAdd(&g_LNP[(size_t)r0 * 3 + 0], sA1);
                    atomicAdd(&g_LNP[(size_t)r0 * 3 + 1], sA2);
                    atomicAdd(&g_LNP[(size_t)r0 * 3 + 2], sA3);
                }
                if (v1) {
                    atomicAdd(&g_LNP[(size_t)(r0 + 8) * 3 + 0], sB1);
                    atomicAdd(&g_LNP[(size_t)(r0 + 8) * 3 + 1], sB2);
                    atomicAdd(&g_LNP[(size_t)(r0 + 8) * 3 + 2], sB3);
                }
            }
        }
    }
}

// ---------------- fused gate + top-3 (PERT never hits gmem) ----------------
__global__ __launch_bounds__(256) void gate_top3_kernel(
    const float* __restrict__ bgp, const float* __restrict__ temp,
    const float* __restrict__ gumbel)
{
    int b = blockIdx.x, tid = threadIdx.x;   // 256 threads, 8 t each
    float c0 = g_CONST[0], c1 = g_CONST[1];
    float bg = bgp[0], invT = 1.f / temp[0];
    float bv[3] = {-1e30f, -1e30f, -1e30f};
    int   bi[3] = {0, 0, 0};
    for (int t = tid; t < TCTX; t += 256) {
        size_t m = (size_t)(b * TFULL + t);
        float S1 = g_LNP[m * 3 + 0];
        float S2 = g_LNP[m * 3 + 1];
        float S3 = g_LNP[m * 3 + 2];
        float mu = S1 * (1.f / 512.f);
        float rs = rsqrtf(S2 * (1.f / 512.f) - mu * mu + 1e-5f);
        float v = (rs * (S3 - mu * c0) + c1 + bg + gumbel[b * TCTX + t]) * invT;
        if (v > bv[0]) { bv[2]=bv[1]; bi[2]=bi[1]; bv[1]=bv[0]; bi[1]=bi[0]; bv[0]=v; bi[0]=t; }
        else if (v > bv[1]) { bv[2]=bv[1]; bi[2]=bi[1]; bv[1]=v; bi[1]=t; }
        else if (v > bv[2]) { bv[2]=v; bi[2]=t; }
    }
    __shared__ float sv[768];
    __shared__ int   si[768];
    sv[tid*3+0]=bv[0]; sv[tid*3+1]=bv[1]; sv[tid*3+2]=bv[2];
    si[tid*3+0]=bi[0]; si[tid*3+1]=bi[1]; si[tid*3+2]=bi[2];
    __syncthreads();
    if (tid == 0) {
        float rv[3] = {-1e30f, -1e30f, -1e30f};
        int   ri[3] = {0, 0, 0};
        for (int e = 0; e < 768; e++) {
            float v = sv[e]; int i = si[e];
            if (v > rv[0]) { rv[2]=rv[1]; ri[2]=ri[1]; rv[1]=rv[0]; ri[1]=ri[0]; rv[0]=v; ri[0]=i; }
            else if (v > rv[1]) { rv[2]=rv[1]; ri[2]=ri[1]; rv[1]=v; ri[1]=i; }
            else if (v > rv[2]) { rv[2]=v; ri[2]=i; }
        }
        g_IDX[b*3+0]=ri[0]; g_IDX[b*3+1]=ri[1]; g_IDX[b*3+2]=ri[2];
    }
}

// ---------------- memory attention (recomputes LN for its 4 rows; fp16 x) ----------------
__global__ __launch_bounds__(512) void attn_kernel(
    const float* __restrict__ Wr, const float* __restrict__ br,
    const float* __restrict__ gamma, const float* __restrict__ beta)
{
    int b = blockIdx.x, tid = threadIdx.x;   // 512 threads (one per d)
    __shared__ float hlast[D];
    __shared__ float gh[3][D];
    __shared__ float red[4][2][16];
    __shared__ float stats[4][2];
    __shared__ float red2[48];
    __shared__ float s_attn[3];
    size_t base = (size_t)b * TFULL * D;
    int i0 = g_IDX[b*3+0], i1 = g_IDX[b*3+1], i2 = g_IDX[b*3+2];
    int rows[4] = {TCTX, i0, i1, i2};

    int lane = tid & 31, w = tid >> 5;
    float xval[4], s[4], q[4];
    #pragma unroll
    for (int r = 0; r < 4; r++) {
        float v = __half2float(g_Hx[base + (size_t)rows[r] * D + tid]);
        xval[r] = v;
        s[r] = v; q[r] = v * v;
    }
    #pragma unroll
    for (int o = 16; o > 0; o >>= 1)
        #pragma unroll
        for (int r = 0; r < 4; r++) {
            s[r] += __shfl_xor_sync(0xffffffffu, s[r], o);
            q[r] += __shfl_xor_sync(0xffffffffu, q[r], o);
        }
    if (lane == 0)
        #pragma unroll
        for (int r = 0; r < 4; r++) { red[r][0][w] = s[r]; red[r][1][w] = q[r]; }
    __syncthreads();
    if (tid < 4) {
        float S = 0.f, Q = 0.f;
        #pragma unroll
        for (int i = 0; i < 16; i++) { S += red[tid][0][i]; Q += red[tid][1][i]; }
        float mu = S * (1.f / 512.f);
        stats[tid][0] = mu;
        stats[tid][1] = rsqrtf(Q * (1.f / 512.f) - mu * mu + 1e-5f);
    }
    __syncthreads();
    float gm = gamma[tid], bt = beta[tid];
    hlast[tid] = (xval[0] - stats[0][0]) * stats[0][1] * gm + bt;
    gh[0][tid] = (xval[1] - stats[1][0]) * stats[1][1] * gm + bt;
    gh[1][tid] = (xval[2] - stats[2][0]) * stats[2][1] * gm + bt;
    gh[2][tid] = (xval[3] - stats[3][0]) * stats[3][1] * gm + bt;
    __syncthreads();

    float qv = br[tid];
    #pragma unroll 4
    for (int j = 0; j < D; j++)
        qv += hlast[j] * Wr[(size_t)j * D + tid];

    float p0 = gh[0][tid] * qv, p1 = gh[1][tid] * qv, p2 = gh[2][tid] * qv;
    #pragma unroll
    for (int o = 16; o > 0; o >>= 1) {
        p0 += __shfl_down_sync(0xffffffffu, p0, o);
        p1 += __shfl_down_sync(0xffffffffu, p1, o);
        p2 += __shfl_down_sync(0xffffffffu, p2, o);
    }
    if (lane == 0) { red2[w] = p0; red2[16 + w] = p1; red2[32 + w] = p2; }
    __syncthreads();
    if (tid == 0) {
        float s0 = 0.f, s1 = 0.f, s2 = 0.f;
        for (int i = 0; i < 16; i++) { s0 += red2[i]; s1 += red2[16+i]; s2 += red2[32+i]; }
        float mx = fmaxf(fmaxf(s0, s1), fmaxf(s2, 0.f));
        float e0 = expf(s0 - mx), e1 = expf(s1 - mx), e2 = expf(s2 - mx);
        float den = e0 + e1 + e2 + 13.f * expf(-mx);
        s_attn[0] = e0 / den; s_attn[1] = e1 / den; s_attn[2] = e2 / den;
    }
    __syncthreads();
    g_CTX[b * D + tid] = s_attn[0]*gh[0][tid] + s_attn[1]*gh[1][tid] + s_attn[2]*gh[2][tid];
}

// ---------------- out = ctx @ Wo + bo  (64 x 50257, K=512), Wo read ONCE, f32x2 ----------------
__global__ __launch_bounds__(256) void out_gemm(
    const float* __restrict__ Wo, const float* __restrict__ bo,
    float* __restrict__ out)
{
    __shared__ float sc[64 * 66];            // [k][row] transposed, padded
    int tid = threadIdx.x;
    int n  = blockIdx.x * 128 + (tid & 127);
    int rh = tid >> 7;                       // 0 or 1 -> rows [0,32) or [32,64)
    bool valid = (n < VOCAB);

    unsigned long long acc2[16];
    #pragma unroll
    for (int j = 0; j < 16; j++) acc2[j] = 0ull;

    for (int k0 = 0; k0 < 512; k0 += 64) {
        __syncthreads();
        #pragma unroll
        for (int i = tid; i < 64 * 64; i += 256) {
            int row = i >> 6, k = i & 63;
            sc[k * 66 + row] = g_CTX[row * 512 + k0 + k];
        }
        __syncthreads();
        if (valid) {
            #pragma unroll 4
            for (int k = 0; k < 64; k++) {
                float w = Wo[(size_t)(k0 + k) * VOCAB + n];
                unsigned long long wd;
                asm("mov.b64 %0, {%1, %1};" : "=l"(wd) : "r"(__float_as_uint(w)));
                const unsigned long long* sp =
                    reinterpret_cast<const unsigned long long*>(sc + k * 66 + rh * 32);
                #pragma unroll
                for (int j = 0; j < 16; j++)
                    asm("fma.rn.f32x2 %0, %1, %2, %0;" : "+l"(acc2[j]) : "l"(sp[j]), "l"(wd));
            }
        }
    }
    if (valid) {
        float b = bo[n];
        #pragma unroll
        for (int j = 0; j < 16; j++) {
            unsigned lo, hi;
            asm("mov.b64 {%0, %1}, %2;" : "=r"(lo), "=r"(hi) : "l"(acc2[j]));
            out[(size_t)(rh * 32 + 2 * j)     * VOCAB + n] = __uint_as_float(lo) + b;
            out[(size_t)(rh * 32 + 2 * j + 1) * VOCAB + n] = __uint_as_float(hi) + b;
        }
    }
}

// ---------------- launch ----------------
extern "C" void kernel_launch(void* const* d_in, const int* in_sizes, int n_in,
                              void* d_out, int out_size)
{
    const int*   seq    = (const int*)  d_in[0];
    const float* temp   = (const float*)d_in[1];
    const float* gumbel = (const float*)d_in[2];
    const float* embed  = (const float*)d_in[3];
    const float* W1     = (const float*)d_in[4];
    const float* b1     = (const float*)d_in[5];
    const float* W2     = (const float*)d_in[6];
    const float* b2     = (const float*)d_in[7];
    const float* gamma  = (const float*)d_in[8];
    const float* beta   = (const float*)d_in[9];
    const float* Wg     = (const float*)d_in[10];
    const float* bg     = (const float*)d_in[11];
    const float* Wr     = (const float*)d_in[12];
    const float* br     = (const float*)d_in[13];
    const float* Wo     = (const float*)d_in[14];
    const float* bo     = (const float*)d_in[15];
    float* out = (float*)d_out;

    __half *pHx, *pHh, *pA1h, *pW1h, *pW2h;
    cudaGetSymbolAddress((void**)&pHx,  g_Hx);
    cudaGetSymbolAddress((void**)&pHh,  g_Hh);
    cudaGetSymbolAddress((void**)&pA1h, g_A1h);
    cudaGetSymbolAddress((void**)&pW1h, g_W1h);
    cudaGetSymbolAddress((void**)&pW2h, g_W2h);

    cudaFuncSetAttribute(ff_gemm<0>, cudaFuncAttributeMaxDynamicSharedMemorySize, GEMM_SMEM);
    cudaFuncSetAttribute(ff_gemm<1>, cudaFuncAttributeMaxDynamicSharedMemorySize, GEMM_SMEM);

    // 0. weight prep + gamma*Wg constants
    wprep<<<(D * D2 + 255) / 256, 256>>>(W1, pW1h, D, D2);
    wprep<<<(D2 * D + 255) / 256, 256>>>(W2, pW2h, D2, D);
    prep_gw<<<1, 512>>>(gamma, beta, Wg);

    // 1. gather embeddings -> fp16; zero LN partials
    gather_kernel<<<MTOK / 8, 256>>>(seq, embed);

    const int MT = (MTOK + 127) / 128;   // 1025

    // 2. A1 = relu(H @ W1 + b1) -> fp16
    ff_gemm<0><<<dim3(D2 / 128, MT), 256, GEMM_SMEM>>>(
        pHh, pW1h, b1, nullptr, nullptr, pA1h, MTOK, D2, D);

    // 3. x = A1 @ W2 + b2 + embed[seq] -> fp16 g_Hx + LN partial sums (fp32)
    ff_gemm<1><<<dim3(D / 128, MT), 256, GEMM_SMEM>>>(
        pA1h, pW2h, b2, seq, embed, pHx, MTOK, D, D2);

    // 4. fused gate + top-3
    gate_top3_kernel<<<BATCH, 256>>>(bg, temp, gumbel);

    // 5. memory attention -> ctx
    attn_kernel<<<BATCH, 512>>>(Wr, br, gamma, beta);

    // 6. out = ctx @ Wo + bo  (f32x2 packed)
    out_gemm<<<(VOCAB + 127) / 128, 256>>>(Wo, bo, out);
}

// round 16
// speedup vs baseline: 1.0013x; 1.0013x over previous
#include <cuda_runtime.h>
#include <cuda_fp16.h>
#include <math.h>
#include <cstdint>

// ---------------- problem constants ----------------
constexpr int BATCH = 64;
constexpr int TFULL = 2049;
constexpr int TCTX  = 2048;
constexpr int D     = 512;
constexpr int D2    = 1024;
constexpr int VOCAB = 50257;
constexpr int MTOK  = BATCH * TFULL;   // 131136

// ---------------- scratch (device globals) ----------------
__device__ float   g_H  [(size_t)MTOK * D];    // x = h + ff, fp32 (written by GEMM2)
__device__ __half  g_Hh [(size_t)MTOK * D];
__device__ __half  g_A1h[(size_t)MTOK * D2];
__device__ __half  g_W1h[(size_t)D2 * D];      // W1^T fp16  [N=D2, K=D]
__device__ __half  g_W2h[(size_t)D * D2];      // W2^T fp16  [N=D,  K=D2]
__device__ float   g_LNP[(size_t)MTOK * 3];    // per-row partials: Sx, Sxx, SxgW
__device__ float   g_GW [D];                   // gamma*Wg
__device__ float   g_CONST[2];                 // {sum(gamma*Wg), sum(beta*Wg)}
__device__ int     g_IDX [BATCH * 3];
__device__ float   g_CTX [BATCH * D];

// ---------------- PTX helpers (base-target features only) ----------------
__device__ __forceinline__ unsigned smem_u32(const void* p) {
    unsigned a;
    asm("{ .reg .u64 t; cvta.to.shared.u64 t, %1; cvt.u32.u64 %0, t; }" : "=r"(a) : "l"(p));
    return a;
}
__device__ __forceinline__ void cp16(unsigned dst, const void* src, int sz) {
    asm volatile("cp.async.cg.shared.global [%0], [%1], 16, %2;"
                 :: "r"(dst), "l"(src), "r"(sz) : "memory");
}
__device__ __forceinline__ void ldsm4(unsigned& r0, unsigned& r1, unsigned& r2, unsigned& r3,
                                      unsigned addr) {
    asm volatile("ldmatrix.sync.aligned.m8n8.x4.shared.b16 {%0,%1,%2,%3}, [%4];"
                 : "=r"(r0), "=r"(r1), "=r"(r2), "=r"(r3) : "r"(addr));
}
__device__ __forceinline__ void mma_f16(float* c, const unsigned* a, const unsigned* b) {
    asm volatile("mma.sync.aligned.m16n8k16.row.col.f32.f16.f16.f32 "
                 "{%0,%1,%2,%3}, {%4,%5,%6,%7}, {%8,%9}, {%0,%1,%2,%3};"
                 : "+f"(c[0]), "+f"(c[1]), "+f"(c[2]), "+f"(c[3])
                 : "r"(a[0]), "r"(a[1]), "r"(a[2]), "r"(a[3]), "r"(b[0]), "r"(b[1]));
}
__device__ __forceinline__ unsigned pack_half2(float v0, float v1) {
    __half h0 = __float2half_rn(v0);
    __half h1 = __float2half_rn(v1);
    return (unsigned)__half_as_ushort(h0) | ((unsigned)__half_as_ushort(h1) << 16);
}

// ---------------- prep: gamma*Wg array + scalar constants ----------------
__global__ void prep_gw(const float* __restrict__ gamma, const float* __restrict__ beta,
                        const float* __restrict__ Wg)
{
    int t = threadIdx.x;                    // 512 threads
    float gw = gamma[t] * Wg[t];
    float bw = beta[t]  * Wg[t];
    g_GW[t] = gw;
    __shared__ float s1[16], s2[16];
    #pragma unroll
    for (int o = 16; o > 0; o >>= 1) {
        gw += __shfl_xor_sync(0xffffffffu, gw, o);
        bw += __shfl_xor_sync(0xffffffffu, bw, o);
    }
    int lane = t & 31, w = t >> 5;
    if (lane == 0) { s1[w] = gw; s2[w] = bw; }
    __syncthreads();
    if (t == 0) {
        float a = 0.f, b = 0.f;
        #pragma unroll
        for (int i = 0; i < 16; i++) { a += s1[i]; b += s2[i]; }
        g_CONST[0] = a; g_CONST[1] = b;
    }
}

// ---------------- fused prep: gather (+LNP zero) | W1 transpose | W2 transpose ----------------
// blocks [0, MTOK/8): gather.  [MTOK/8, +2048): W1.  [+2048, +4096): W2.
constexpr int GATHER_BLOCKS = MTOK / 8;          // 16392
constexpr int WP_BLOCKS     = (D * D2) / 256;    // 2048

__global__ __launch_bounds__(256) void prep_all(
    const int* __restrict__ seq, const float* __restrict__ embed,
    const float* __restrict__ W1, const float* __restrict__ W2)
{
    int bid = blockIdx.x;
    if (bid < GATHER_BLOCKS) {
        int w = threadIdx.x >> 5, lane = threadIdx.x & 31;
        int m = bid * 8 + w;
        int tok = seq[m];
        if (lane < 3) g_LNP[(size_t)m * 3 + lane] = 0.f;
        const float4* src = reinterpret_cast<const float4*>(embed + (size_t)tok * D);
        uint2* dstHh = reinterpret_cast<uint2*>(g_Hh + (size_t)m * D);
        #pragma unroll
        for (int i = 0; i < 4; i++) {
            int j = lane + 32 * i;
            float4 v = src[j];
            uint2 p;
            p.x = pack_half2(v.x, v.y);
            p.y = pack_half2(v.z, v.w);
            dstHh[j] = p;
        }
    } else if (bid < GATHER_BLOCKS + WP_BLOCKS) {
        int i = (bid - GATHER_BLOCKS) * 256 + threadIdx.x;   // W1: [D, D2]
        int k = i / D2, n = i - k * D2;
        g_W1h[(size_t)n * D + k] = __float2half_rn(W1[i]);
    } else {
        int i = (bid - GATHER_BLOCKS - WP_BLOCKS) * 256 + threadIdx.x;   // W2: [D2, D]
        int k = i / D, n = i - k * D;
        g_W2h[(size_t)n * D2 + k] = __float2half_rn(W2[i]);
    }
}

// ---------------- mma.sync fp16 GEMM, CTA 128x128, warp 32x64, BK=32, 4-stage ----------------
// Conflict-free smem: 48-byte row stride. Slice (k16) = 128*48 = 6144B.
// Stage = A[2 slices] + B[2 slices] = 24576B. A slice s at s*6144; B at 12288+s*6144.
// 4 stages = 98304B -> 2 CTAs/SM.
// Wait ladder (CORRECT): at iter c, only stages c+1, c+2 may be pending -> wait_group 2.
// MODE 0: relu -> fp16 out.  MODE 1: +bias + embed residual -> fp32 x out + LN partials.
constexpr int SLICE_BYTES = 6144;
constexpr int STAGE_BYTES = 24576;
constexpr int GEMM_SMEM   = 4 * STAGE_BYTES;   // 98304

__device__ __forceinline__ void fill_stage(unsigned sb,
    const __half* __restrict__ Ah, const __half* __restrict__ Bh,
    int K, int m0, int M, int n0, int kc, int tid)
{
    int r = tid >> 1, half = tid & 1;
    int arow = m0 + r;
    int asz  = (arow < M) ? 16 : 0;
    size_t aoff = (size_t)(asz ? arow : 0) * K + kc + half * 8;
    size_t boff = (size_t)(n0 + r) * K + kc + half * 8;
    unsigned dst = sb + r * 48 + half * 16;
    #pragma unroll
    for (int s = 0; s < 2; s++) {
        cp16(dst + s * SLICE_BYTES,         Ah + aoff + s * 16, asz);
        cp16(dst + 12288 + s * SLICE_BYTES, Bh + boff + s * 16, 16);
    }
    asm volatile("cp.async.commit_group;" ::: "memory");
}

template<int MODE>
__global__ __launch_bounds__(256, 2) void ff_gemm(
    const __half* __restrict__ Ah, const __half* __restrict__ Bh,
    const float* __restrict__ bias,
    const int* __restrict__ seq, const float* __restrict__ embed,
    __half* __restrict__ Ch, float* __restrict__ Cf, int M, int N, int K)
{
    extern __shared__ __align__(128) char smem[];
    unsigned sb = smem_u32(smem);
    const int tid = threadIdx.x, lane = tid & 31, wid = tid >> 5;
    const int wm = wid & 3, wn = wid >> 2;
    const int m0 = blockIdx.y * 128, n0 = blockIdx.x * 128;

    // per-lane ldmatrix offsets (within a k16-slice; 48B row stride)
    const unsigned aO = (unsigned)((wm * 32 + (lane & 15)) * 48 + (lane >> 4) * 16);
    const unsigned bO = 12288u +
        (unsigned)((wn * 64 + (lane >> 4) * 8 + (lane & 7)) * 48 + ((lane >> 3) & 1) * 16);

    float acc[2][8][4];
    #pragma unroll
    for (int i = 0; i < 2; i++)
        #pragma unroll
        for (int j = 0; j < 8; j++)
            #pragma unroll
            for (int q = 0; q < 4; q++) acc[i][j][q] = 0.f;

    const int NC = K >> 5;
    fill_stage(sb + 0 * STAGE_BYTES, Ah, Bh, K, m0, M, n0, 0,  tid);
    fill_stage(sb + 1 * STAGE_BYTES, Ah, Bh, K, m0, M, n0, 32, tid);
    fill_stage(sb + 2 * STAGE_BYTES, Ah, Bh, K, m0, M, n0, 64, tid);

    int sidx = 0;
    for (int c = 0; c < NC; c++) {
        int rem = NC - 1 - c;
        // stage c complete; only c+1, c+2 may remain pending
        if (rem >= 2)      asm volatile("cp.async.wait_group 2;" ::: "memory");
        else if (rem == 1) asm volatile("cp.async.wait_group 1;" ::: "memory");
        else               asm volatile("cp.async.wait_group 0;" ::: "memory");
        __syncthreads();

        unsigned st = sb + sidx * STAGE_BYTES;

        // slice 0 loads first (start LDS latency ASAP)
        unsigned ah[2][4], bh[8][2];
        #pragma unroll
        for (int mt = 0; mt < 2; mt++)
            ldsm4(ah[mt][0], ah[mt][1], ah[mt][2], ah[mt][3], st + aO + mt * 768);
        #pragma unroll
        for (int pr = 0; pr < 4; pr++)
            ldsm4(bh[2*pr][0], bh[2*pr][1], bh[2*pr+1][0], bh[2*pr+1][1],
                  st + bO + pr * 768);

        // prefetch next stage while slice-0 fragments are in flight
        int pf = c + 3;
        if (pf < NC) {
            int psidx = sidx + 3; if (psidx >= 4) psidx -= 4;
            fill_stage(sb + psidx * STAGE_BYTES, Ah, Bh, K, m0, M, n0, pf * 32, tid);
        }

        #pragma unroll
        for (int mt = 0; mt < 2; mt++)
            #pragma unroll
            for (int nt = 0; nt < 8; nt++)
                mma_f16(acc[mt][nt], ah[mt], bh[nt]);

        // slice 1
        #pragma unroll
        for (int mt = 0; mt < 2; mt++)
            ldsm4(ah[mt][0], ah[mt][1], ah[mt][2], ah[mt][3],
                  st + SLICE_BYTES + aO + mt * 768);
        #pragma unroll
        for (int pr = 0; pr < 4; pr++)
            ldsm4(bh[2*pr][0], bh[2*pr][1], bh[2*pr+1][0], bh[2*pr+1][1],
                  st + SLICE_BYTES + bO + pr * 768);
        #pragma unroll
        for (int mt = 0; mt < 2; mt++)
            #pragma unroll
            for (int nt = 0; nt < 8; nt++)
                mma_f16(acc[mt][nt], ah[mt], bh[nt]);

        if (++sidx == 4) sidx = 0;
    }

    // ---------------- epilogue ----------------
    const int g = lane >> 2, t4 = lane & 3;
    #pragma unroll
    for (int mt = 0; mt < 2; mt++) {
        int r0 = m0 + wm * 32 + mt * 16 + g;
        bool v0 = (r0 < M), v1 = (r0 + 8 < M);
        if (MODE == 0) {
            #pragma unroll
            for (int nt = 0; nt < 8; nt++) {
                int n = n0 + wn * 64 + nt * 8 + t4 * 2;
                float b0 = bias[n], b1 = bias[n + 1];
                if (v0)
                    *reinterpret_cast<unsigned*>(Ch + (size_t)r0 * N + n) =
                        pack_half2(fmaxf(acc[mt][nt][0] + b0, 0.f),
                                   fmaxf(acc[mt][nt][1] + b1, 0.f));
                if (v1)
                    *reinterpret_cast<unsigned*>(Ch + (size_t)(r0 + 8) * N + n) =
                        pack_half2(fmaxf(acc[mt][nt][2] + b0, 0.f),
                                   fmaxf(acc[mt][nt][3] + b1, 0.f));
            }
        } else {
            int tok0 = v0 ? seq[r0] : 0;
            int tok1 = v1 ? seq[r0 + 8] : 0;
            float sA1 = 0.f, sA2 = 0.f, sA3 = 0.f;
            float sB1 = 0.f, sB2 = 0.f, sB3 = 0.f;
            #pragma unroll
            for (int nt = 0; nt < 8; nt++) {
                int n = n0 + wn * 64 + nt * 8 + t4 * 2;
                float b0 = bias[n], b1 = bias[n + 1];
                float2 gw = *reinterpret_cast<const float2*>(g_GW + n);
                if (v0) {
                    float2 a = *reinterpret_cast<const float2*>(embed + (size_t)tok0 * D + n);
                    float x0 = acc[mt][nt][0] + b0 + a.x;
                    float x1 = acc[mt][nt][1] + b1 + a.y;
                    *reinterpret_cast<float2*>(Cf + (size_t)r0 * N + n) = make_float2(x0, x1);
                    sA1 += x0 + x1; sA2 += x0 * x0 + x1 * x1;
                    sA3 += x0 * gw.x + x1 * gw.y;
                }
                if (v1) {
                    float2 a = *reinterpret_cast<const float2*>(embed + (size_t)tok1 * D + n);
                    float x0 = acc[mt][nt][2] + b0 + a.x;
                    float x1 = acc[mt][nt][3] + b1 + a.y;
                    *reinterpret_cast<float2*>(Cf + (size_t)(r0 + 8) * N + n) = make_float2(x0, x1);
                    sB1 += x0 + x1; sB2 += x0 * x0 + x1 * x1;
                    sB3 += x0 * gw.x + x1 * gw.y;
                }
            }
            #pragma unroll
            for (int o = 1; o < 4; o <<= 1) {
                sA1 += __shfl_down_sync(0xffffffffu, sA1, o);
                sA2 += __shfl_down_sync(0xffffffffu, sA2, o);
                sA3 += __shfl_down_sync(0xffffffffu, sA3, o);
                sB1 += __shfl_down_sync(0xffffffffu, sB1, o);
                sB2 += __shfl_down_sync(0xffffffffu, sB2, o);
                sB3 += __shfl_down_sync(0xffffffffu, sB3, o);
            }
            if (t4 == 0) {
                if (v0) {
                    atomicAdd(&g_LNP[(size_t)r0 * 3 + 0], sA1);
                    atomicAdd(&g_LNP[(size_t)r0 * 3 + 1], sA2);
                    atomicAdd(&g_LNP[(size_t)r0 * 3 + 2], sA3);
                }
                if (v1) {
                    atomicAdd(&g_LNP[(size_t)(r0 + 8) * 3 + 0], sB1);
                    atomicAdd(&g_LNP[(size_t)(r0 + 8) * 3 + 1], sB2);
                    atomicAdd(&g_LNP[(size_t)(r0 + 8) * 3 + 2], sB3);
                }
            }
        }
    }
}

// ---------------- fused gate + top-3 (PERT never hits gmem) ----------------
__global__ __launch_bounds__(256) void gate_top3_kernel(
    const float* __restrict__ bgp, const float* __restrict__ temp,
    const float* __restrict__ gumbel)
{
    int b = blockIdx.x, tid = threadIdx.x;   // 256 threads, 8 t each
    float c0 = g_CONST[0], c1 = g_CONST[1];
    float bg = bgp[0], invT = 1.f / temp[0];
    float bv[3] = {-1e30f, -1e30f, -1e30f};
    int   bi[3] = {0, 0, 0};
    for (int t = tid; t < TCTX; t += 256) {
        size_t m = (size_t)(b * TFULL + t);
        float S1 = g_LNP[m * 3 + 0];
        float S2 = g_LNP[m * 3 + 1];
        float S3 = g_LNP[m * 3 + 2];
        float mu = S1 * (1.f / 512.f);
        float rs = rsqrtf(S2 * (1.f / 512.f) - mu * mu + 1e-5f);
        float v = (rs * (S3 - mu * c0) + c1 + bg + gumbel[b * TCTX + t]) * invT;
        if (v > bv[0]) { bv[2]=bv[1]; bi[2]=bi[1]; bv[1]=bv[0]; bi[1]=bi[0]; bv[0]=v; bi[0]=t; }
        else if (v > bv[1]) { bv[2]=bv[1]; bi[2]=bi[1]; bv[1]=v; bi[1]=t; }
        else if (v > bv[2]) { bv[2]=v; bi[2]=t; }
    }
    __shared__ float sv[768];
    __shared__ int   si[768];
    sv[tid*3+0]=bv[0]; sv[tid*3+1]=bv[1]; sv[tid*3+2]=bv[2];
    si[tid*3+0]=bi[0]; si[tid*3+1]=bi[1]; si[tid*3+2]=bi[2];
    __syncthreads();
    if (tid == 0) {
        float rv[3] = {-1e30f, -1e30f, -1e30f};
        int   ri[3] = {0, 0, 0};
        for (int e = 0; e < 768; e++) {
            float v = sv[e]; int i = si[e];
            if (v > rv[0]) { rv[2]=rv[1]; ri[2]=ri[1]; rv[1]=rv[0]; ri[1]=ri[0]; rv[0]=v; ri[0]=i; }
            else if (v > rv[1]) { rv[2]=rv[1]; ri[2]=ri[1]; rv[1]=v; ri[1]=i; }
            else if (v > rv[2]) { rv[2]=v; ri[2]=i; }
        }
        g_IDX[b*3+0]=ri[0]; g_IDX[b*3+1]=ri[1]; g_IDX[b*3+2]=ri[2];
    }
}

// ---------------- memory attention (recomputes LN for its 4 rows; fp32 x) ----------------
__global__ __launch_bounds__(512) void attn_kernel(
    const float* __restrict__ Wr, const float* __restrict__ br,
    const float* __restrict__ gamma, const float* __restrict__ beta)
{
    int b = blockIdx.x, tid = threadIdx.x;   // 512 threads (one per d)
    __shared__ float hlast[D];
    __shared__ float gh[3][D];
    __shared__ float red[4][2][16];
    __shared__ float stats[4][2];
    __shared__ float red2[48];
    __shared__ float s_attn[3];
    size_t base = (size_t)b * TFULL * D;
    int i0 = g_IDX[b*3+0], i1 = g_IDX[b*3+1], i2 = g_IDX[b*3+2];
    int rows[4] = {TCTX, i0, i1, i2};

    int lane = tid & 31, w = tid >> 5;
    float xval[4], s[4], q[4];
    #pragma unroll
    for (int r = 0; r < 4; r++) {
        float v = g_H[base + (size_t)rows[r] * D + tid];
        xval[r] = v;
        s[r] = v; q[r] = v * v;
    }
    #pragma unroll
    for (int o = 16; o > 0; o >>= 1)
        #pragma unroll
        for (int r = 0; r < 4; r++) {
            s[r] += __shfl_xor_sync(0xffffffffu, s[r], o);
            q[r] += __shfl_xor_sync(0xffffffffu, q[r], o);
        }
    if (lane == 0)
        #pragma unroll
        for (int r = 0; r < 4; r++) { red[r][0][w] = s[r]; red[r][1][w] = q[r]; }
    __syncthreads();
    if (tid < 4) {
        float S = 0.f, Q = 0.f;
        #pragma unroll
        for (int i = 0; i < 16; i++) { S += red[tid][0][i]; Q += red[tid][1][i]; }
        float mu = S * (1.f / 512.f);
        stats[tid][0] = mu;
        stats[tid][1] = rsqrtf(Q * (1.f / 512.f) - mu * mu + 1e-5f);
    }
    __syncthreads();
    float gm = gamma[tid], bt = beta[tid];
    hlast[tid] = (xval[0] - stats[0][0]) * stats[0][1] * gm + bt;
    gh[0][tid] = (xval[1] - stats[1][0]) * stats[1][1] * gm + bt;
    gh[1][tid] = (xval[2] - stats[2][0]) * stats[2][1] * gm + bt;
    gh[2][tid] = (xval[3] - stats[3][0]) * stats[3][1] * gm + bt;
    __syncthreads();

    float qv = br[tid];
    #pragma unroll 4
    for (int j = 0; j < D; j++)
        qv += hlast[j] * Wr[(size_t)j * D + tid];

    float p0 = gh[0][tid] * qv, p1 = gh[1][tid] * qv, p2 = gh[2][tid] * qv;
    #pragma unroll
    for (int o = 16; o > 0; o >>= 1) {
        p0 += __shfl_down_sync(0xffffffffu, p0, o);
        p1 += __shfl_down_sync(0xffffffffu, p1, o);
        p2 += __shfl_down_sync(0xffffffffu, p2, o);
    }
    if (lane == 0) { red2[w] = p0; red2[16 + w] = p1; red2[32 + w] = p2; }
    __syncthreads();
    if (tid == 0) {
        float s0 = 0.f, s1 = 0.f, s2 = 0.f;
        for (int i = 0; i < 16; i++) { s0 += red2[i]; s1 += red2[16+i]; s2 += red2[32+i]; }
        float mx = fmaxf(fmaxf(s0, s1), fmaxf(s2, 0.f));
        float e0 = expf(s0 - mx), e1 = expf(s1 - mx), e2 = expf(s2 - mx);
        float den = e0 + e1 + e2 + 13.f * expf(-mx);
        s_attn[0] = e0 / den; s_attn[1] = e1 / den; s_attn[2] = e2 / den;
    }
    __syncthreads();
    g_CTX[b * D + tid] = s_attn[0]*gh[0][tid] + s_attn[1]*gh[1][tid] + s_attn[2]*gh[2][tid];
}

// ---------------- out = ctx @ Wo + bo  (64 x 50257, K=512), Wo read ONCE, f32x2 ----------------
__global__ __launch_bounds__(256) void out_gemm(
    const float* __restrict__ Wo, const float* __restrict__ bo,
    float* __restrict__ out)
{
    __shared__ float sc[64 * 66];            // [k][row] transposed, padded
    int tid = threadIdx.x;
    int n  = blockIdx.x * 128 + (tid & 127);
    int rh = tid >> 7;                       // 0 or 1 -> rows [0,32) or [32,64)
    bool valid = (n < VOCAB);

    unsigned long long acc2[16];
    #pragma unroll
    for (int j = 0; j < 16; j++) acc2[j] = 0ull;

    for (int k0 = 0; k0 < 512; k0 += 64) {
        __syncthreads();
        #pragma unroll
        for (int i = tid; i < 64 * 64; i += 256) {
            int row = i >> 6, k = i & 63;
            sc[k * 66 + row] = g_CTX[row * 512 + k0 + k];
        }
        __syncthreads();
        if (valid) {
            #pragma unroll 4
            for (int k = 0; k < 64; k++) {
                float w = Wo[(size_t)(k0 + k) * VOCAB + n];
                unsigned long long wd;
                asm("mov.b64 %0, {%1, %1};" : "=l"(wd) : "r"(__float_as_uint(w)));
                const unsigned long long* sp =
                    reinterpret_cast<const unsigned long long*>(sc + k * 66 + rh * 32);
                #pragma unroll
                for (int j = 0; j < 16; j++)
                    asm("fma.rn.f32x2 %0, %1, %2, %0;" : "+l"(acc2[j]) : "l"(sp[j]), "l"(wd));
            }
        }
    }
    if (valid) {
        float b = bo[n];
        #pragma unroll
        for (int j = 0; j < 16; j++) {
            unsigned lo, hi;
            asm("mov.b64 {%0, %1}, %2;" : "=r"(lo), "=r"(hi) : "l"(acc2[j]));
            out[(size_t)(rh * 32 + 2 * j)     * VOCAB + n] = __uint_as_float(lo) + b;
            out[(size_t)(rh * 32 + 2 * j + 1) * VOCAB + n] = __uint_as_float(hi) + b;
        }
    }
}

// ---------------- launch ----------------
extern "C" void kernel_launch(void* const* d_in, const int* in_sizes, int n_in,
                              void* d_out, int out_size)
{
    const int*   seq    = (const int*)  d_in[0];
    const float* temp   = (const float*)d_in[1];
    const float* gumbel = (const float*)d_in[2];
    const float* embed  = (const float*)d_in[3];
    const float* W1     = (const float*)d_in[4];
    const float* b1     = (const float*)d_in[5];
    const float* W2     = (const float*)d_in[6];
    const float* b2     = (const float*)d_in[7];
    const float* gamma  = (const float*)d_in[8];
    const float* beta   = (const float*)d_in[9];
    const float* Wg     = (const float*)d_in[10];
    const float* bg     = (const float*)d_in[11];
    const float* Wr     = (const float*)d_in[12];
    const float* br     = (const float*)d_in[13];
    const float* Wo     = (const float*)d_in[14];
    const float* bo     = (const float*)d_in[15];
    float* out = (float*)d_out;

    float *pH;
    __half *pHh, *pA1h, *pW1h, *pW2h;
    cudaGetSymbolAddress((void**)&pH,   g_H);
    cudaGetSymbolAddress((void**)&pHh,  g_Hh);
    cudaGetSymbolAddress((void**)&pA1h, g_A1h);
    cudaGetSymbolAddress((void**)&pW1h, g_W1h);
    cudaGetSymbolAddress((void**)&pW2h, g_W2h);

    cudaFuncSetAttribute(ff_gemm<0>, cudaFuncAttributeMaxDynamicSharedMemorySize, GEMM_SMEM);
    cudaFuncSetAttribute(ff_gemm<1>, cudaFuncAttributeMaxDynamicSharedMemorySize, GEMM_SMEM);

    // 0. gamma*Wg constants (tiny, independent)
    prep_gw<<<1, 512>>>(gamma, beta, Wg);

    // 1. fused prep: gather + both weight transposes in ONE launch
    prep_all<<<GATHER_BLOCKS + 2 * WP_BLOCKS, 256>>>(seq, embed, W1, W2);

    const int MT = (MTOK + 127) / 128;   // 1025

    // 2. A1 = relu(H @ W1 + b1) -> fp16
    ff_gemm<0><<<dim3(D2 / 128, MT), 256, GEMM_SMEM>>>(
        pHh, pW1h, b1, nullptr, nullptr, pA1h, nullptr, MTOK, D2, D);

    // 3. x = A1 @ W2 + b2 + embed[seq] -> fp32 g_H + LN partial sums
    ff_gemm<1><<<dim3(D / 128, MT), 256, GEMM_SMEM>>>(
        pA1h, pW2h, b2, seq, embed, nullptr, pH, MTOK, D, D2);

    // 4. fused gate + top-3
    gate_top3_kernel<<<BATCH, 256>>>(bg, temp, gumbel);

    // 5. memory attention -> ctx
    attn_kernel<<<BATCH, 512>>>(Wr, br, gamma, beta);

    // 6. out = ctx @ Wo + bo  (f32x2 packed)
    out_gemm<<<(VOCAB + 127) / 128, 256>>>(Wo, bo, out);
}